// round 1
// baseline (speedup 1.0000x reference)
#include <cuda_runtime.h>

// Problem constants (fixed by the dataset): N = 1,000,000 points, C = 64.
#define C 64
#define NMAX 1000000

// Scratch (allocation-free): two ping-pong intermediate buffers + BN stats.
__device__ float g_h1[(size_t)NMAX * C];
__device__ float g_h2[(size_t)NMAX * C];
__device__ float g_sum[C];
__device__ float g_sumsq[C];

__global__ void zero_stats_kernel() {
    if (threadIdx.x < C) {
        g_sum[threadIdx.x] = 0.f;
        g_sumsq[threadIdx.x] = 0.f;
    }
}

// One sparse conv layer: out[n][c] = sum_k sum_ci feats[nbr[n][k]][ci] * W[k][ci][c]
// Block = 256 threads = 4 points x 64 channels. W staged in dynamic shared (48KB).
// STATS: also accumulate per-channel sum/sumsq of the output (for BatchNorm).
template <bool STATS>
__global__ void __launch_bounds__(256) conv_kernel(
    const float* __restrict__ in,   // [N, 64]
    const float* __restrict__ W,    // [3, 64, 64]
    const int*   __restrict__ nbr,  // [N, 3]
    float*       __restrict__ out,  // [N, 64]
    int N)
{
    extern __shared__ float sW[];            // [3*64*64] = 48KB
    __shared__ float4 sF[4][3][16];          // gathered feats rows (4 pts x 3 taps x 64 f)
    __shared__ int    sN[4][3];              // neighbor indices
    __shared__ float  sStat[2][256];

    // Stage weights
    #pragma unroll 4
    for (int i = threadIdx.x; i < 3 * C * C; i += 256) sW[i] = W[i];

    const int p = threadIdx.x >> 6;   // point lane 0..3
    const int c = threadIdx.x & 63;   // output channel

    float lsum = 0.f, lsq = 0.f;

    for (int base = blockIdx.x * 4; base < N; base += gridDim.x * 4) {
        const int n = base + p;
        __syncthreads();  // protects sW on iter 0, sF/sN reuse afterwards
        if (n < N && c < 3) sN[p][c] = nbr[n * 3 + c];
        __syncthreads();
        if (n < N) {
            #pragma unroll
            for (int k = 0; k < 3; k++) {
                const int idx = sN[p][k];
                ((float*)sF[p][k])[c] = (idx >= 0) ? in[idx * C + c] : 0.f;
            }
        }
        __syncthreads();
        if (n < N) {
            float acc = 0.f;
            #pragma unroll
            for (int k = 0; k < 3; k++) {
                if (sN[p][k] < 0) continue;   // warp-uniform skip (both warps of lane p agree)
                const float* w = &sW[k * (C * C) + c];
                #pragma unroll
                for (int q = 0; q < 16; q++) {
                    const float4 f = sF[p][k][q];    // broadcast LDS.128
                    acc = fmaf(f.x, w[(4 * q + 0) * C], acc);
                    acc = fmaf(f.y, w[(4 * q + 1) * C], acc);
                    acc = fmaf(f.z, w[(4 * q + 2) * C], acc);
                    acc = fmaf(f.w, w[(4 * q + 3) * C], acc);
                }
            }
            out[n * C + c] = acc;
            if (STATS) { lsum += acc; lsq += acc * acc; }
        }
    }

    if (STATS) {
        sStat[0][threadIdx.x] = lsum;
        sStat[1][threadIdx.x] = lsq;
        __syncthreads();
        if (threadIdx.x < C) {
            const float s = sStat[0][c] + sStat[0][c + 64] + sStat[0][c + 128] + sStat[0][c + 192];
            const float q = sStat[1][c] + sStat[1][c + 64] + sStat[1][c + 128] + sStat[1][c + 192];
            atomicAdd(&g_sum[c], s);
            atomicAdd(&g_sumsq[c], q);
        }
    }
}

// BatchNorm (batch stats) + ReLU, float4-vectorized.
__global__ void __launch_bounds__(256) bn_relu_kernel(
    const float* __restrict__ h,      // [N, 64]
    const float* __restrict__ gamma,
    const float* __restrict__ beta,
    float*       __restrict__ out,
    int N)
{
    __shared__ float sScale[C], sShift[C];
    if (threadIdx.x < C) {
        const int ch = threadIdx.x;
        const float invN = 1.f / (float)N;
        const float mean = g_sum[ch] * invN;
        float var = g_sumsq[ch] * invN - mean * mean;
        var = fmaxf(var, 0.f);
        const float sc = gamma[ch] * rsqrtf(var + 1e-5f);
        sScale[ch] = sc;
        sShift[ch] = beta[ch] - mean * sc;
    }
    __syncthreads();

    const int nvec = N * (C / 4);   // number of float4s (64M/4 = 16M, fits int)
    for (int i = blockIdx.x * blockDim.x + threadIdx.x; i < nvec;
         i += gridDim.x * blockDim.x) {
        float4 v = ((const float4*)h)[i];
        const int c0 = (i & 15) << 2;   // (4*i) % 64
        v.x = fmaxf(fmaf(v.x, sScale[c0 + 0], sShift[c0 + 0]), 0.f);
        v.y = fmaxf(fmaf(v.y, sScale[c0 + 1], sShift[c0 + 1]), 0.f);
        v.z = fmaxf(fmaf(v.z, sScale[c0 + 2], sShift[c0 + 2]), 0.f);
        v.w = fmaxf(fmaf(v.w, sScale[c0 + 3], sShift[c0 + 3]), 0.f);
        ((float4*)out)[i] = v;
    }
}

extern "C" void kernel_launch(void* const* d_in, const int* in_sizes, int n_in,
                              void* d_out, int out_size)
{
    const float* feats = (const float*)d_in[0];
    const float* W1    = (const float*)d_in[1];
    const float* W2    = (const float*)d_in[2];
    const float* W3    = (const float*)d_in[3];
    const float* gamma = (const float*)d_in[4];
    const float* beta  = (const float*)d_in[5];
    const int* nbr_z   = (const int*)d_in[6];
    const int* nbr_y   = (const int*)d_in[7];
    const int* nbr_x   = (const int*)d_in[8];
    float* out = (float*)d_out;

    const int N = in_sizes[0] / C;

    const int SMEM_W = 3 * C * C * (int)sizeof(float);  // 48KB dynamic
    cudaFuncSetAttribute(conv_kernel<false>,
                         cudaFuncAttributeMaxDynamicSharedMemorySize, SMEM_W);
    cudaFuncSetAttribute(conv_kernel<true>,
                         cudaFuncAttributeMaxDynamicSharedMemorySize, SMEM_W);

    float* h1;  cudaGetSymbolAddress((void**)&h1, g_h1);
    float* h2;  cudaGetSymbolAddress((void**)&h2, g_h2);

    zero_stats_kernel<<<1, 64>>>();

    const int GRID = 148 * 4;
    conv_kernel<false><<<GRID, 256, SMEM_W>>>(feats, W1, nbr_z, h1, N);
    conv_kernel<false><<<GRID, 256, SMEM_W>>>(h1,    W2, nbr_y, h2, N);
    conv_kernel<true ><<<GRID, 256, SMEM_W>>>(h2,    W3, nbr_x, h1, N);

    bn_relu_kernel<<<2048, 256>>>(h1, gamma, beta, out, N);
}

// round 2
// speedup vs baseline: 2.4314x; 2.4314x over previous
#include <cuda_runtime.h>

#define NMAX 1000000
#define MAXHITS 262144
#define AP 68   // sA pitch in floats

// Scratch (allocation-free)
__device__ float g_h1[(size_t)NMAX * 64];
__device__ float g_h2[(size_t)NMAX * 64];
__device__ float g_sum[64];
__device__ float g_sumsq[64];
__device__ int   g_cnt[3];
__device__ int4  g_hits[3][MAXHITS];

__global__ void zero_kernel() {
    int t = threadIdx.x;
    if (t < 64) { g_sum[t] = 0.f; g_sumsq[t] = 0.f; }
    if (t < 3)  g_cnt[t] = 0;
}

// Build per-layer hit lists: one entry per point having >=1 side tap.
__global__ void __launch_bounds__(256) compact_kernel(
    const int* __restrict__ nz, const int* __restrict__ ny,
    const int* __restrict__ nx, int N)
{
    const int L = blockIdx.y;
    const int* nb = (L == 0) ? nz : ((L == 1) ? ny : nx);
    const int n = blockIdx.x * 256 + threadIdx.x;
    int i0 = -1, i2 = -1;
    bool has = false;
    if (n < N) {
        i0 = nb[3 * n + 0];
        i2 = nb[3 * n + 2];
        has = (i0 >= 0) | (i2 >= 0);
    }
    unsigned m = __ballot_sync(0xffffffffu, has);
    if (!m) return;
    const int lane = threadIdx.x & 31;
    const int leader = __ffs(m) - 1;
    int base = 0;
    if (lane == leader) base = atomicAdd(&g_cnt[L], __popc(m));
    base = __shfl_sync(0xffffffffu, base, leader);
    if (has) {
        int off = base + __popc(m & ((1u << lane) - 1));
        if (off < MAXHITS) g_hits[L][off] = make_int4(n, i0, i2, 0);
    }
}

// Dense GEMM: out[m][c] = sum_k in[m][k] * Wmid[k][c].
// Tile 256 pts x 64 ch, 256 threads. Warp w owns channels [8w,8w+8);
// lane l owns points {l + 32*mi}. 8x8 register accumulators.
__global__ void __launch_bounds__(256, 2) dense_kernel(
    const float* __restrict__ in, const float* __restrict__ Wmid,
    float* __restrict__ out, int N)
{
    extern __shared__ float sm[];
    float* sA = sm;              // [256][AP]
    float* sB = sm + 256 * AP;   // [64][64]

    const int t = threadIdx.x;
    #pragma unroll
    for (int i = t; i < 1024; i += 256)
        ((float4*)sB)[i] = ((const float4*)Wmid)[i];

    const int m0 = blockIdx.x * 256;
    {
        const int mbase = t >> 4;
        const int k = (t & 15) * 4;
        #pragma unroll
        for (int r = 0; r < 16; r++) {
            const int mm = mbase + r * 16;
            float4 v = make_float4(0.f, 0.f, 0.f, 0.f);
            if (m0 + mm < N) v = *(const float4*)(in + (size_t)(m0 + mm) * 64 + k);
            *(float4*)(sA + mm * AP + k) = v;
        }
    }
    __syncthreads();

    const int warp = t >> 5;
    const int lane = t & 31;
    const int c0 = warp * 8;

    float acc[8][8];
    #pragma unroll
    for (int i = 0; i < 8; i++)
        #pragma unroll
        for (int j = 0; j < 8; j++) acc[i][j] = 0.f;

    #pragma unroll 4
    for (int kb = 0; kb < 64; kb += 2) {
        float2 a[8];
        #pragma unroll
        for (int mi = 0; mi < 8; mi++)
            a[mi] = *(const float2*)(sA + (lane + 32 * mi) * AP + kb);
        const float4 b00 = *(const float4*)(sB + (kb + 0) * 64 + c0);
        const float4 b01 = *(const float4*)(sB + (kb + 0) * 64 + c0 + 4);
        const float4 b10 = *(const float4*)(sB + (kb + 1) * 64 + c0);
        const float4 b11 = *(const float4*)(sB + (kb + 1) * 64 + c0 + 4);
        #pragma unroll
        for (int mi = 0; mi < 8; mi++) {
            acc[mi][0] = fmaf(a[mi].x, b00.x, acc[mi][0]);
            acc[mi][1] = fmaf(a[mi].x, b00.y, acc[mi][1]);
            acc[mi][2] = fmaf(a[mi].x, b00.z, acc[mi][2]);
            acc[mi][3] = fmaf(a[mi].x, b00.w, acc[mi][3]);
            acc[mi][4] = fmaf(a[mi].x, b01.x, acc[mi][4]);
            acc[mi][5] = fmaf(a[mi].x, b01.y, acc[mi][5]);
            acc[mi][6] = fmaf(a[mi].x, b01.z, acc[mi][6]);
            acc[mi][7] = fmaf(a[mi].x, b01.w, acc[mi][7]);
            acc[mi][0] = fmaf(a[mi].y, b10.x, acc[mi][0]);
            acc[mi][1] = fmaf(a[mi].y, b10.y, acc[mi][1]);
            acc[mi][2] = fmaf(a[mi].y, b10.z, acc[mi][2]);
            acc[mi][3] = fmaf(a[mi].y, b10.w, acc[mi][3]);
            acc[mi][4] = fmaf(a[mi].y, b11.x, acc[mi][4]);
            acc[mi][5] = fmaf(a[mi].y, b11.y, acc[mi][5]);
            acc[mi][6] = fmaf(a[mi].y, b11.z, acc[mi][6]);
            acc[mi][7] = fmaf(a[mi].y, b11.w, acc[mi][7]);
        }
    }

    #pragma unroll
    for (int mi = 0; mi < 8; mi++) {
        const int m = m0 + lane + 32 * mi;
        if (m < N) {
            float4 v0 = make_float4(acc[mi][0], acc[mi][1], acc[mi][2], acc[mi][3]);
            float4 v1 = make_float4(acc[mi][4], acc[mi][5], acc[mi][6], acc[mi][7]);
            *(float4*)(out + (size_t)m * 64 + c0) = v0;
            *(float4*)(out + (size_t)m * 64 + c0 + 4) = v1;
        }
    }
}

// Sparse correction: out[n] += g(i0) @ W[0] + g(i2) @ W[2] for hit entries.
// 128 threads, 4 entries per iteration. Side-tap weights live in registers:
// thread (c = t&63, half = t>>6) holds W[tap][half*32+j][c].
__global__ void __launch_bounds__(128) sparse_kernel(
    const float* __restrict__ in, const float* __restrict__ W,
    float* __restrict__ out, int L)
{
    __shared__ float sG[4][2][64];
    __shared__ float sP[4][2][64];

    const int t = threadIdx.x;
    const int c = t & 63;
    const int half = t >> 6;

    float w0[32], w2[32];
    #pragma unroll
    for (int j = 0; j < 32; j++) {
        w0[j] = W[(half * 32 + j) * 64 + c];
        w2[j] = W[2 * 4096 + (half * 32 + j) * 64 + c];
    }

    const int cnt = min(g_cnt[L], MAXHITS);
    const int4* hits = g_hits[L];

    for (int e0 = blockIdx.x * 4; e0 < cnt; e0 += gridDim.x * 4) {
        __syncthreads();   // protect sG/sP reuse from previous iteration
        {
            const int e = t >> 5, tap = (t >> 4) & 1, q = t & 15;
            if (e0 + e < cnt) {
                const int4 ent = hits[e0 + e];
                const int idx = tap ? ent.z : ent.y;
                if (idx >= 0)
                    *(float4*)&sG[e][tap][q * 4] =
                        *(const float4*)(in + (size_t)idx * 64 + q * 4);
            }
        }
        __syncthreads();
        #pragma unroll
        for (int e = 0; e < 4; e++) {
            if (e0 + e >= cnt) break;
            const int4 ent = hits[e0 + e];
            float p = 0.f;
            if (ent.y >= 0) {
                #pragma unroll
                for (int j = 0; j < 32; j += 4) {
                    const float4 g = *(const float4*)&sG[e][0][half * 32 + j];
                    p = fmaf(g.x, w0[j + 0], p);
                    p = fmaf(g.y, w0[j + 1], p);
                    p = fmaf(g.z, w0[j + 2], p);
                    p = fmaf(g.w, w0[j + 3], p);
                }
            }
            if (ent.z >= 0) {
                #pragma unroll
                for (int j = 0; j < 32; j += 4) {
                    const float4 g = *(const float4*)&sG[e][1][half * 32 + j];
                    p = fmaf(g.x, w2[j + 0], p);
                    p = fmaf(g.y, w2[j + 1], p);
                    p = fmaf(g.z, w2[j + 2], p);
                    p = fmaf(g.w, w2[j + 3], p);
                }
            }
            sP[e][half][c] = p;
        }
        __syncthreads();
        #pragma unroll
        for (int r = 0; r < 2; r++) {
            const int slot = t + r * 128;
            const int e = slot >> 6, cc = slot & 63;
            if (e0 + e < cnt) {
                const int n = hits[e0 + e].x;
                out[(size_t)n * 64 + cc] += sP[e][0][cc] + sP[e][1][cc];
            }
        }
    }
}

// Per-channel sum / sumsq of h.
__global__ void __launch_bounds__(256) stat_kernel(const float* __restrict__ h, int N)
{
    __shared__ float ss[2][256];
    const int t = threadIdx.x;
    const int c = t & 63, g = t >> 6;
    float s = 0.f, q = 0.f;
    for (int n = blockIdx.x * 4 + g; n < N; n += gridDim.x * 4) {
        const float v = h[(size_t)n * 64 + c];
        s += v;
        q = fmaf(v, v, q);
    }
    ss[0][t] = s; ss[1][t] = q;
    __syncthreads();
    if (t < 64) {
        const float S = ss[0][t] + ss[0][t + 64] + ss[0][t + 128] + ss[0][t + 192];
        const float Q = ss[1][t] + ss[1][t + 64] + ss[1][t + 128] + ss[1][t + 192];
        atomicAdd(&g_sum[t], S);
        atomicAdd(&g_sumsq[t], Q);
    }
}

__global__ void __launch_bounds__(256) bn_relu_kernel(
    const float* __restrict__ h, const float* __restrict__ gamma,
    const float* __restrict__ beta, float* __restrict__ out, int N)
{
    __shared__ float sScale[64], sShift[64];
    if (threadIdx.x < 64) {
        const int ch = threadIdx.x;
        const float invN = 1.f / (float)N;
        const float mean = g_sum[ch] * invN;
        float var = g_sumsq[ch] * invN - mean * mean;
        var = fmaxf(var, 0.f);
        const float sc = gamma[ch] * rsqrtf(var + 1e-5f);
        sScale[ch] = sc;
        sShift[ch] = beta[ch] - mean * sc;
    }
    __syncthreads();

    const int nvec = N * 16;
    for (int i = blockIdx.x * blockDim.x + threadIdx.x; i < nvec;
         i += gridDim.x * blockDim.x) {
        float4 v = ((const float4*)h)[i];
        const int c0 = (i & 15) << 2;
        v.x = fmaxf(fmaf(v.x, sScale[c0 + 0], sShift[c0 + 0]), 0.f);
        v.y = fmaxf(fmaf(v.y, sScale[c0 + 1], sShift[c0 + 1]), 0.f);
        v.z = fmaxf(fmaf(v.z, sScale[c0 + 2], sShift[c0 + 2]), 0.f);
        v.w = fmaxf(fmaf(v.w, sScale[c0 + 3], sShift[c0 + 3]), 0.f);
        ((float4*)out)[i] = v;
    }
}

extern "C" void kernel_launch(void* const* d_in, const int* in_sizes, int n_in,
                              void* d_out, int out_size)
{
    const float* feats = (const float*)d_in[0];
    const float* W1    = (const float*)d_in[1];
    const float* W2    = (const float*)d_in[2];
    const float* W3    = (const float*)d_in[3];
    const float* gamma = (const float*)d_in[4];
    const float* beta  = (const float*)d_in[5];
    const int* nbr_z   = (const int*)d_in[6];
    const int* nbr_y   = (const int*)d_in[7];
    const int* nbr_x   = (const int*)d_in[8];
    float* out = (float*)d_out;

    const int N = in_sizes[0] / 64;

    const int SMEM = (256 * AP + 64 * 64) * (int)sizeof(float);  // 86016 B
    cudaFuncSetAttribute(dense_kernel,
                         cudaFuncAttributeMaxDynamicSharedMemorySize, SMEM);

    float* h1; cudaGetSymbolAddress((void**)&h1, g_h1);
    float* h2; cudaGetSymbolAddress((void**)&h2, g_h2);

    zero_kernel<<<1, 64>>>();
    compact_kernel<<<dim3((N + 255) / 256, 3), 256>>>(nbr_z, nbr_y, nbr_x, N);

    const int GT = (N + 255) / 256;
    dense_kernel<<<GT, 256, SMEM>>>(feats, W1 + 4096, h1, N);
    sparse_kernel<<<592, 128>>>(feats, W1, h1, 0);
    dense_kernel<<<GT, 256, SMEM>>>(h1, W2 + 4096, h2, N);
    sparse_kernel<<<592, 128>>>(h1, W2, h2, 1);
    dense_kernel<<<GT, 256, SMEM>>>(h2, W3 + 4096, h1, N);
    sparse_kernel<<<592, 128>>>(h2, W3, h1, 2);

    stat_kernel<<<1184, 256>>>(h1, N);
    bn_relu_kernel<<<2048, 256>>>(h1, gamma, beta, out, N);
}

// round 3
// speedup vs baseline: 2.8557x; 1.1745x over previous
#include <cuda_runtime.h>
#include <cstdint>

#define NMAX 1000000
#define MAXHITS 262144
#define AP 66    // dense sA pitch (floats): bank stride 2 -> conflict-free phases
#define GP 130   // sparse sG pitch (floats)

// Scratch (allocation-free)
__device__ float g_h1[(size_t)NMAX * 64];
__device__ float g_h2[(size_t)NMAX * 64];
__device__ float g_sum[64];
__device__ float g_sumsq[64];
__device__ int   g_cnt[3];
__device__ int4  g_hits[3][MAXHITS];

// ---- f32x2 packed math (PTX-only on sm_103a; 2x FFMA issue rate) ----
__device__ __forceinline__ unsigned long long dup2(float x) {
    unsigned long long r;
    asm("mov.b64 %0, {%1, %1};" : "=l"(r) : "f"(x));
    return r;
}
__device__ __forceinline__ void dfma2(unsigned long long& d,
                                      unsigned long long a,
                                      unsigned long long b) {
    asm("fma.rn.f32x2 %0, %1, %2, %0;" : "+l"(d) : "l"(a), "l"(b));
}
__device__ __forceinline__ unsigned long long dadd2(unsigned long long a,
                                                    unsigned long long b) {
    unsigned long long r;
    asm("add.rn.f32x2 %0, %1, %2;" : "=l"(r) : "l"(a), "l"(b));
    return r;
}
__device__ __forceinline__ void cp8(void* smem_dst, const void* gsrc, int nbytes) {
    uint32_t d = (uint32_t)__cvta_generic_to_shared(smem_dst);
    asm volatile("cp.async.ca.shared.global [%0], [%1], 8, %2;"
                 :: "r"(d), "l"(gsrc), "r"(nbytes));
}

__global__ void zero_kernel() {
    int t = threadIdx.x;
    if (t < 64) { g_sum[t] = 0.f; g_sumsq[t] = 0.f; }
    if (t < 3)  g_cnt[t] = 0;
}

// Build per-layer hit lists: one entry per point having >=1 side tap.
__global__ void __launch_bounds__(256) compact_kernel(
    const int* __restrict__ nz, const int* __restrict__ ny,
    const int* __restrict__ nx, int N)
{
    const int L = blockIdx.y;
    const int* nb = (L == 0) ? nz : ((L == 1) ? ny : nx);
    const int n = blockIdx.x * 256 + threadIdx.x;
    int i0 = -1, i2 = -1;
    bool has = false;
    if (n < N) {
        i0 = nb[3 * n + 0];
        i2 = nb[3 * n + 2];
        has = (i0 >= 0) | (i2 >= 0);
    }
    unsigned m = __ballot_sync(0xffffffffu, has);
    if (!m) return;
    const int lane = threadIdx.x & 31;
    const int leader = __ffs(m) - 1;
    int base = 0;
    if (lane == leader) base = atomicAdd(&g_cnt[L], __popc(m));
    base = __shfl_sync(0xffffffffu, base, leader);
    if (has) {
        int off = base + __popc(m & ((1u << lane) - 1));
        if (off < MAXHITS) g_hits[L][off] = make_int4(n, i0, i2, 0);
    }
}

// Dense GEMM: out[m][c] = sum_k in[m][k] * Wmid[k][c].
// Tile 256 pts x 64 ch, 256 threads. Warp w: channels [(w&3)*16, +16),
// point-half (w>>2)*128; lane owns points {half + lane + 32*mi}, mi<4.
// acc = 4 pts x 8 channel-pairs of f32x2.
__global__ void __launch_bounds__(256, 2) dense_kernel(
    const float* __restrict__ in, const float* __restrict__ Wmid,
    float* __restrict__ out, int N)
{
    extern __shared__ float sm[];
    float* sA = sm;              // [256][AP]
    float* sB = sm + 256 * AP;   // [64][64]

    const int t = threadIdx.x;
    const int lane = t & 31;
    const int w = t >> 5;

    // Stage B (16KB)
    #pragma unroll
    for (int i = t; i < 1024; i += 256)
        ((float4*)sB)[i] = ((const float4*)Wmid)[i];

    // Stage A via cp.async (8B each, warp stages whole 256B rows)
    const int m0 = blockIdx.x * 256;
    #pragma unroll
    for (int j = 0; j < 32; j++) {
        const int row = j * 8 + w;
        int gr = m0 + row; if (gr >= N) gr = N - 1;
        cp8(sA + row * AP + lane * 2, in + (size_t)gr * 64 + lane * 2, 8);
    }
    asm volatile("cp.async.commit_group;");
    asm volatile("cp.async.wait_group 0;");
    __syncthreads();

    const int c0 = (w & 3) * 16;
    const int rbase = (w >> 2) * 128 + lane;

    unsigned long long acc[4][8];
    #pragma unroll
    for (int i = 0; i < 4; i++)
        #pragma unroll
        for (int p = 0; p < 8; p++) acc[i][p] = 0ull;

    #pragma unroll 4
    for (int kb = 0; kb < 64; kb += 2) {
        float2 av[4];
        #pragma unroll
        for (int mi = 0; mi < 4; mi++)
            av[mi] = *(const float2*)(sA + (rbase + 32 * mi) * AP + kb);
        #pragma unroll
        for (int kk = 0; kk < 2; kk++) {
            const ulonglong2* bp =
                (const ulonglong2*)(sB + (kb + kk) * 64 + c0);
            const ulonglong2 q0 = bp[0], q1 = bp[1], q2 = bp[2], q3 = bp[3];
            unsigned long long b[8] = {q0.x, q0.y, q1.x, q1.y,
                                       q2.x, q2.y, q3.x, q3.y};
            #pragma unroll
            for (int mi = 0; mi < 4; mi++) {
                const unsigned long long a2 = dup2(kk ? av[mi].y : av[mi].x);
                #pragma unroll
                for (int p = 0; p < 8; p++) dfma2(acc[mi][p], a2, b[p]);
            }
        }
    }

    #pragma unroll
    for (int mi = 0; mi < 4; mi++) {
        const int m = m0 + rbase + 32 * mi;
        if (m < N) {
            ulonglong2* op = (ulonglong2*)(out + (size_t)m * 64 + c0);
            op[0] = make_ulonglong2(acc[mi][0], acc[mi][1]);
            op[1] = make_ulonglong2(acc[mi][2], acc[mi][3]);
            op[2] = make_ulonglong2(acc[mi][4], acc[mi][5]);
            op[3] = make_ulonglong2(acc[mi][6], acc[mi][7]);
        }
    }
}

// Sparse correction, GEMM-tiled: for each hit entry (n,i0,i2):
//   out[n][c] += in[i0] @ W[0] + in[i2] @ W[2]
// Tile = 64 entries x 64 ch, K = 128 (tap0 k:0-63, tap2 k:64-127), 256 threads.
// Missing taps zero-filled by cp.async (size 0). Warp w: channels (w&3)*16,
// entry-half (w>>2)*32; lane owns 1 entry. Non-atomic RMW (entries unique).
__global__ void __launch_bounds__(256, 2) sparse_kernel(
    const float* __restrict__ in, const float* __restrict__ W,
    float* __restrict__ out, int L)
{
    extern __shared__ float sm[];
    float* sW = sm;              // [128][64]: rows 0-63 = W[0], 64-127 = W[2]
    float* sG = sm + 128 * 64;   // [64][GP]

    const int t = threadIdx.x;
    const int lane = t & 31;
    const int w = t >> 5;

    // Stage W[0] and W[2] (skip W[1])
    #pragma unroll
    for (int i = t; i < 2048; i += 256)
        ((float4*)sW)[i] = ((const float4*)W)[i < 1024 ? i : i + 1024];

    const int cnt = min(g_cnt[L], MAXHITS);
    const int4* hits = g_hits[L];

    const int c0 = (w & 3) * 16;
    const int e = (w >> 2) * 32 + lane;   // this thread's entry within tile

    for (int tile = blockIdx.x; tile * 64 < cnt; tile += gridDim.x) {
        const int e0 = tile * 64;
        __syncthreads();   // protect sG reuse

        // Gather: 128 (entry,tap) rows x 32 float2; warp stages row pair/iter
        #pragma unroll
        for (int j = 0; j < 16; j++) {
            const int pair = j * 8 + w;
            const int ge = pair >> 1, tap = pair & 1;
            if (e0 + ge < cnt) {
                const int4 ent = __ldg(&hits[e0 + ge]);
                const int idx = tap ? ent.z : ent.y;
                const int sz = (idx >= 0) ? 8 : 0;
                const float* src = in + (size_t)(idx >= 0 ? idx : 0) * 64 + lane * 2;
                cp8(sG + ge * GP + tap * 64 + lane * 2, src, sz);
            }
        }
        asm volatile("cp.async.commit_group;");
        asm volatile("cp.async.wait_group 0;");
        __syncthreads();

        unsigned long long acc[8];
        #pragma unroll
        for (int p = 0; p < 8; p++) acc[p] = 0ull;

        #pragma unroll 4
        for (int kb = 0; kb < 128; kb += 2) {
            const float2 av = *(const float2*)(sG + e * GP + kb);
            #pragma unroll
            for (int kk = 0; kk < 2; kk++) {
                const ulonglong2* bp =
                    (const ulonglong2*)(sW + (kb + kk) * 64 + c0);
                const ulonglong2 q0 = bp[0], q1 = bp[1], q2 = bp[2], q3 = bp[3];
                const unsigned long long a2 = dup2(kk ? av.y : av.x);
                dfma2(acc[0], a2, q0.x); dfma2(acc[1], a2, q0.y);
                dfma2(acc[2], a2, q1.x); dfma2(acc[3], a2, q1.y);
                dfma2(acc[4], a2, q2.x); dfma2(acc[5], a2, q2.y);
                dfma2(acc[6], a2, q3.x); dfma2(acc[7], a2, q3.y);
            }
        }

        if (e0 + e < cnt) {
            const int n = __ldg(&hits[e0 + e].x);
            ulonglong2* op = (ulonglong2*)(out + (size_t)n * 64 + c0);
            #pragma unroll
            for (int q = 0; q < 4; q++) {
                ulonglong2 cur = op[q];
                cur.x = dadd2(cur.x, acc[2 * q + 0]);
                cur.y = dadd2(cur.y, acc[2 * q + 1]);
                op[q] = cur;
            }
        }
    }
}

// Per-channel sum / sumsq of h.
__global__ void __launch_bounds__(256) stat_kernel(const float* __restrict__ h, int N)
{
    __shared__ float ss[2][256];
    const int t = threadIdx.x;
    const int c = t & 63, g = t >> 6;
    float s = 0.f, q = 0.f;
    for (int n = blockIdx.x * 4 + g; n < N; n += gridDim.x * 4) {
        const float v = h[(size_t)n * 64 + c];
        s += v;
        q = fmaf(v, v, q);
    }
    ss[0][t] = s; ss[1][t] = q;
    __syncthreads();
    if (t < 64) {
        const float S = ss[0][t] + ss[0][t + 64] + ss[0][t + 128] + ss[0][t + 192];
        const float Q = ss[1][t] + ss[1][t + 64] + ss[1][t + 128] + ss[1][t + 192];
        atomicAdd(&g_sum[t], S);
        atomicAdd(&g_sumsq[t], Q);
    }
}

__global__ void __launch_bounds__(256) bn_relu_kernel(
    const float* __restrict__ h, const float* __restrict__ gamma,
    const float* __restrict__ beta, float* __restrict__ out, int N)
{
    __shared__ float sScale[64], sShift[64];
    if (threadIdx.x < 64) {
        const int ch = threadIdx.x;
        const float invN = 1.f / (float)N;
        const float mean = g_sum[ch] * invN;
        float var = g_sumsq[ch] * invN - mean * mean;
        var = fmaxf(var, 0.f);
        const float sc = gamma[ch] * rsqrtf(var + 1e-5f);
        sScale[ch] = sc;
        sShift[ch] = beta[ch] - mean * sc;
    }
    __syncthreads();

    const int nvec = N * 16;
    for (int i = blockIdx.x * blockDim.x + threadIdx.x; i < nvec;
         i += gridDim.x * blockDim.x) {
        float4 v = ((const float4*)h)[i];
        const int c0 = (i & 15) << 2;
        v.x = fmaxf(fmaf(v.x, sScale[c0 + 0], sShift[c0 + 0]), 0.f);
        v.y = fmaxf(fmaf(v.y, sScale[c0 + 1], sShift[c0 + 1]), 0.f);
        v.z = fmaxf(fmaf(v.z, sScale[c0 + 2], sShift[c0 + 2]), 0.f);
        v.w = fmaxf(fmaf(v.w, sScale[c0 + 3], sShift[c0 + 3]), 0.f);
        ((float4*)out)[i] = v;
    }
}

extern "C" void kernel_launch(void* const* d_in, const int* in_sizes, int n_in,
                              void* d_out, int out_size)
{
    const float* feats = (const float*)d_in[0];
    const float* W1    = (const float*)d_in[1];
    const float* W2    = (const float*)d_in[2];
    const float* W3    = (const float*)d_in[3];
    const float* gamma = (const float*)d_in[4];
    const float* beta  = (const float*)d_in[5];
    const int* nbr_z   = (const int*)d_in[6];
    const int* nbr_y   = (const int*)d_in[7];
    const int* nbr_x   = (const int*)d_in[8];
    float* out = (float*)d_out;

    const int N = in_sizes[0] / 64;

    const int SMEM_D = (256 * AP + 64 * 64) * (int)sizeof(float);   // 83968 B
    const int SMEM_S = (128 * 64 + 64 * GP) * (int)sizeof(float);   // 66048 B
    cudaFuncSetAttribute(dense_kernel,
                         cudaFuncAttributeMaxDynamicSharedMemorySize, SMEM_D);
    cudaFuncSetAttribute(sparse_kernel,
                         cudaFuncAttributeMaxDynamicSharedMemorySize, SMEM_S);

    float* h1; cudaGetSymbolAddress((void**)&h1, g_h1);
    float* h2; cudaGetSymbolAddress((void**)&h2, g_h2);

    zero_kernel<<<1, 64>>>();
    compact_kernel<<<dim3((N + 255) / 256, 3), 256>>>(nbr_z, nbr_y, nbr_x, N);

    const int GT = (N + 255) / 256;
    dense_kernel<<<GT, 256, SMEM_D>>>(feats, W1 + 4096, h1, N);
    sparse_kernel<<<592, 256, SMEM_S>>>(feats, W1, h1, 0);
    dense_kernel<<<GT, 256, SMEM_D>>>(h1, W2 + 4096, h2, N);
    sparse_kernel<<<592, 256, SMEM_S>>>(h1, W2, h2, 1);
    dense_kernel<<<GT, 256, SMEM_D>>>(h2, W3 + 4096, h1, N);
    sparse_kernel<<<592, 256, SMEM_S>>>(h2, W3, h1, 2);

    stat_kernel<<<1184, 256>>>(h1, N);
    bn_relu_kernel<<<2048, 256>>>(h1, gamma, beta, out, N);
}